// round 6
// baseline (speedup 1.0000x reference)
#include <cuda_runtime.h>
#include <cuda_bf16.h>
#include <math_constants.h>

#define NN 50000
#define EE 800000
#define DD 128
#define NEG_SLOPE 0.2f
#define XS_STRIDE 132   // padded to break bank conflicts

// ---------------- device scratch (static, no allocation) ----------------
__device__ float g_h[(size_t)NN * DD];   // transformed features
__device__ float g_as[NN];
__device__ float g_ad[NN];
__device__ int   g_deg[NN];
__device__ int   g_off[NN + 1];
__device__ int   g_cur[NN];
__device__ int   g_pos[EE];              // CSR slot per edge (built in fork stream)
__device__ int   g_ssrc[EE];             // edge src sorted by dst (fork stream)
__device__ float g_es[EE];               // exp(leaky(e)) sorted by dst

// ---------------- 1) GEMM: h = x @ W, fused a_s/a_d epilogue ----------------
// 128x128x128 block tile, blockDim (16,16) = 256 thr, 8x8 register microtile.
// Measured standalone: 54.7us, fma pipe 40.9% (R2 profile).
__global__ void gat_gemm(const float* __restrict__ x, const float* __restrict__ W,
                         const float* __restrict__ att_s, const float* __restrict__ att_d)
{
    extern __shared__ float sm[];
    float* xs = sm;                       // [128][XS_STRIDE]
    float* ws = sm + 128 * XS_STRIDE;     // [128][128] (k-major, same as W)

    const int tx = threadIdx.x, ty = threadIdx.y;
    const int tid = ty * 16 + tx;
    const int m0 = blockIdx.x * 128;

    // load W (128x128 = 4096 float4)
    #pragma unroll
    for (int t = 0; t < 16; t++) {
        int idx = tid + 256 * t;
        ((float4*)ws)[idx] = ((const float4*)W)[idx];
    }
    // load x tile [128][128] into padded xs, zero-pad OOB rows
    #pragma unroll
    for (int t = 0; t < 16; t++) {
        int idx = tid + 256 * t;          // 0..4095
        int r  = idx >> 5;
        int c4 = idx & 31;
        float4 v = make_float4(0.f, 0.f, 0.f, 0.f);
        int row = m0 + r;
        if (row < NN) v = ((const float4*)x)[(size_t)row * 32 + c4];
        ((float4*)(xs + (size_t)r * XS_STRIDE))[c4] = v;
    }
    __syncthreads();

    float acc[8][8];
    #pragma unroll
    for (int i = 0; i < 8; i++)
        #pragma unroll
        for (int j = 0; j < 8; j++) acc[i][j] = 0.f;

    #pragma unroll 8
    for (int k = 0; k < 128; k++) {
        float av[8];
        #pragma unroll
        for (int i = 0; i < 8; i++) av[i] = xs[(ty + 16 * i) * XS_STRIDE + k];
        float4 b0 = ((float4*)(ws + k * 128))[tx * 2];
        float4 b1 = ((float4*)(ws + k * 128))[tx * 2 + 1];
        float bv[8] = {b0.x, b0.y, b0.z, b0.w, b1.x, b1.y, b1.z, b1.w};
        #pragma unroll
        for (int i = 0; i < 8; i++)
            #pragma unroll
            for (int j = 0; j < 8; j++)
                acc[i][j] = fmaf(av[i], bv[j], acc[i][j]);
    }

    // attention vectors for this thread's 8 columns
    float4 s0 = ((const float4*)att_s)[tx * 2];
    float4 s1 = ((const float4*)att_s)[tx * 2 + 1];
    float4 d0 = ((const float4*)att_d)[tx * 2];
    float4 d1 = ((const float4*)att_d)[tx * 2 + 1];

    #pragma unroll
    for (int i = 0; i < 8; i++) {
        int row = m0 + ty + 16 * i;
        if (row < NN) {
            float4 h0 = make_float4(acc[i][0], acc[i][1], acc[i][2], acc[i][3]);
            float4 h1 = make_float4(acc[i][4], acc[i][5], acc[i][6], acc[i][7]);
            ((float4*)(g_h + (size_t)row * 128))[tx * 2]     = h0;
            ((float4*)(g_h + (size_t)row * 128))[tx * 2 + 1] = h1;
        }
        float ps = acc[i][0]*s0.x + acc[i][1]*s0.y + acc[i][2]*s0.z + acc[i][3]*s0.w
                 + acc[i][4]*s1.x + acc[i][5]*s1.y + acc[i][6]*s1.z + acc[i][7]*s1.w;
        float pd = acc[i][0]*d0.x + acc[i][1]*d0.y + acc[i][2]*d0.z + acc[i][3]*d0.w
                 + acc[i][4]*d1.x + acc[i][5]*d1.y + acc[i][6]*d1.z + acc[i][7]*d1.w;
        #pragma unroll
        for (int s = 8; s; s >>= 1) {
            ps += __shfl_xor_sync(0xffffffffu, ps, s);
            pd += __shfl_xor_sync(0xffffffffu, pd, s);
        }
        if (tx == 0 && row < NN) { g_as[row] = ps; g_ad[row] = pd; }
    }
}

// ---------------- 2) CSR build (fork stream — independent of GEMM) ----------------
__global__ void gat_zero_deg()
{
    int i = blockIdx.x * blockDim.x + threadIdx.x;
    if (i < NN) g_deg[i] = 0;
}

__global__ void gat_hist(const int* __restrict__ dst)
{
    int i = blockIdx.x * blockDim.x + threadIdx.x;
    if (i < EE) atomicAdd(&g_deg[dst[i]], 1);
}

// single block, 1024 threads: exclusive scan of degrees -> offsets + cursors
__global__ void gat_scan()
{
    __shared__ int s[1024];
    const int tid = threadIdx.x;
    const int C = (NN + 1023) / 1024;     // 49
    int start = tid * C;
    int end = start + C; if (end > NN) end = NN;
    if (start > NN) start = NN;

    int sum = 0;
    for (int i = start; i < end; i++) sum += g_deg[i];
    s[tid] = sum;
    for (int o = 1; o < 1024; o <<= 1) {
        __syncthreads();
        int v = (tid >= o) ? s[tid - o] : 0;
        __syncthreads();
        s[tid] += v;
    }
    __syncthreads();
    int run = s[tid] - sum;               // exclusive prefix
    for (int i = start; i < end; i++) {
        g_off[i] = run;
        g_cur[i] = run;
        run += g_deg[i];
    }
    if (tid == 1023) g_off[NN] = s[1023]; // = E
}

// assign CSR slot + scatter src index (no dependence on GEMM outputs)
__global__ void gat_build(const int* __restrict__ src, const int* __restrict__ dst)
{
    int i = blockIdx.x * blockDim.x + threadIdx.x;
    if (i >= EE) return;
    int dv = dst[i];
    int pos = atomicAdd(&g_cur[dv], 1);
    g_pos[i]    = pos;
    g_ssrc[pos] = src[i];
}

// ---------------- 3) per-edge p = exp(leakyrelu(a_s[src]+a_d[dst])) ----------------
// softmax is shift-invariant; logits are O(1) so no max-subtraction needed.
__global__ void gat_edge(const int* __restrict__ src, const int* __restrict__ dst)
{
    int i = blockIdx.x * blockDim.x + threadIdx.x;
    if (i >= EE) return;
    float t = g_as[src[i]] + g_ad[dst[i]];
    float e = t > 0.f ? t : NEG_SLOPE * t;
    g_es[g_pos[i]] = __expf(e);
}

// ---------------- 4) per-dst normalize + aggregate + fused epilogue ----------------
// one warp per destination node; gathers batched x4 for MLP
__global__ void gat_aggregate(const float* __restrict__ x,
                              const float* __restrict__ bias,
                              const float* __restrict__ gamma,
                              const float* __restrict__ beta,
                              float* __restrict__ out)
{
    int u = blockIdx.x * (blockDim.x >> 5) + (threadIdx.x >> 5);
    int lane = threadIdx.x & 31;
    if (u >= NN) return;

    int o   = g_off[u];
    int deg = g_off[u + 1] - o;

    float4 acc = make_float4(0.f, 0.f, 0.f, 0.f);

    if (deg > 0) {
        // pass A: denom (contiguous)
        float sum = 0.f;
        for (int j = lane; j < deg; j += 32) sum += g_es[o + j];
        #pragma unroll
        for (int sh = 16; sh; sh >>= 1) sum += __shfl_xor_sync(0xffffffffu, sum, sh);
        float inv = 1.f / sum;

        // pass B: weighted gather, 4 edges in flight
        for (int j0 = 0; j0 < deg; j0 += 4) {
            float p4[4]; int s4[4];
            #pragma unroll
            for (int t = 0; t < 4; t++) {
                int j = j0 + t;
                bool v = j < deg;
                int jj = v ? j : 0;
                s4[t] = g_ssrc[o + jj];
                p4[t] = v ? g_es[o + jj] * inv : 0.f;
            }
            float4 hv4[4];
            #pragma unroll
            for (int t = 0; t < 4; t++)
                hv4[t] = ((const float4*)(g_h + (size_t)s4[t] * 128))[lane];
            #pragma unroll
            for (int t = 0; t < 4; t++) {
                acc.x = fmaf(p4[t], hv4[t].x, acc.x);
                acc.y = fmaf(p4[t], hv4[t].y, acc.y);
                acc.z = fmaf(p4[t], hv4[t].z, acc.z);
                acc.w = fmaf(p4[t], hv4[t].w, acc.w);
            }
        }
    }

    // epilogue: bias -> BN(eval) -> ReLU -> residual
    const float inv_s = rsqrtf(1.0f + 1e-5f);
    float4 bv = ((const float4*)bias)[lane];
    float4 gv = ((const float4*)gamma)[lane];
    float4 be = ((const float4*)beta)[lane];
    float4 xv = ((const float4*)(x + (size_t)u * 128))[lane];

    float4 r;
    r.x = xv.x + fmaxf(gv.x * ((acc.x + bv.x) * inv_s) + be.x, 0.f);
    r.y = xv.y + fmaxf(gv.y * ((acc.y + bv.y) * inv_s) + be.y, 0.f);
    r.z = xv.z + fmaxf(gv.z * ((acc.z + bv.z) * inv_s) + be.z, 0.f);
    r.w = xv.w + fmaxf(gv.w * ((acc.w + bv.w) * inv_s) + be.w, 0.f);

    ((float4*)(out + (size_t)u * 128))[lane] = r;
}

// ---------------- stream/event handles (created pre-baseline, once) ----------------
struct StreamInit {
    cudaStream_t s;
    cudaEvent_t  eFork, eJoin;
    StreamInit() {
        cudaStreamCreateWithFlags(&s, cudaStreamNonBlocking);
        cudaEventCreateWithFlags(&eFork, cudaEventDisableTiming);
        cudaEventCreateWithFlags(&eJoin, cudaEventDisableTiming);
    }
};
static StreamInit g_si;

// ---------------- launch ----------------
extern "C" void kernel_launch(void* const* d_in, const int* in_sizes, int n_in,
                              void* d_out, int out_size)
{
    const float* x        = (const float*)d_in[0];
    const int*   edge     = (const int*)d_in[1];   // [2, E]: src row then dst row
    const float* W        = (const float*)d_in[2];
    const float* att_src  = (const float*)d_in[3];
    const float* att_dst  = (const float*)d_in[4];
    const float* bias     = (const float*)d_in[5];
    const float* gamma    = (const float*)d_in[6];
    const float* beta     = (const float*)d_in[7];
    float* out            = (float*)d_out;

    const int* src = edge;
    const int* dst = edge + EE;

    static const size_t GEMM_SMEM = (128 * XS_STRIDE + 128 * 128) * sizeof(float);
    cudaFuncSetAttribute(gat_gemm, cudaFuncAttributeMaxDynamicSharedMemorySize,
                         (int)GEMM_SMEM);

    // fork: full CSR structure build (depends only on edge_index), hidden under GEMM
    cudaEventRecord(g_si.eFork, 0);
    cudaStreamWaitEvent(g_si.s, g_si.eFork, 0);
    gat_zero_deg<<<(NN + 255) / 256, 256, 0, g_si.s>>>();
    gat_hist<<<(EE + 255) / 256, 256, 0, g_si.s>>>(dst);
    gat_scan<<<1, 1024, 0, g_si.s>>>();
    gat_build<<<(EE + 255) / 256, 256, 0, g_si.s>>>(src, dst);
    cudaEventRecord(g_si.eJoin, g_si.s);

    dim3 gemmBlock(16, 16);
    gat_gemm<<<(NN + 127) / 128, gemmBlock, GEMM_SMEM>>>(x, W, att_src, att_dst);

    // join: edge pass needs a_s/a_d (gemm) + slots (build)
    cudaStreamWaitEvent(0, g_si.eJoin, 0);
    gat_edge<<<(EE + 255) / 256, 256>>>(src, dst);

    gat_aggregate<<<(NN + 7) / 8, 256>>>(x, bias, gamma, beta, out);
}

// round 8
// speedup vs baseline: 1.4771x; 1.4771x over previous
#include <cuda_runtime.h>
#include <cuda_bf16.h>
#include <math_constants.h>

#define NN 50000
#define EE 800000
#define DD 128
#define NEG_SLOPE 0.2f
#define XS_STRIDE 132   // padded to break bank conflicts

// ---------------- device scratch (static, no allocation) ----------------
__device__ float g_h[(size_t)NN * DD];   // transformed features
__device__ float g_as[NN];
__device__ float g_ad[NN];
__device__ int   g_deg[NN];
__device__ int   g_off[NN + 1];
__device__ int   g_cur[NN];
__device__ int   g_pos[EE];              // CSR slot per edge (built in fork stream)
__device__ int   g_ssrc[EE];             // edge src sorted by dst (fork stream)
__device__ float g_es[EE];               // exp(leaky(e)) sorted by dst

// ---------------- 1) GEMM: h = x @ W, fused a_s/a_d epilogue ----------------
// 128x128x128 tile, blockDim (32,16) = 512 thr, 8x4 microtile per thread.
// EMPIRICALLY the good config (R3: 183.3us total). Do not change.
__global__ void gat_gemm(const float* __restrict__ x, const float* __restrict__ W,
                         const float* __restrict__ att_s, const float* __restrict__ att_d)
{
    extern __shared__ float sm[];
    float* xs = sm;                       // [128][XS_STRIDE]
    float* ws = sm + 128 * XS_STRIDE;     // [128][128] (k-major, same as W)

    const int tx = threadIdx.x, ty = threadIdx.y;
    const int tid = ty * 32 + tx;
    const int m0 = blockIdx.x * 128;

    // load W (128x128 = 4096 float4), 8 per thread
    #pragma unroll
    for (int t = 0; t < 8; t++) {
        int idx = tid + 512 * t;
        ((float4*)ws)[idx] = ((const float4*)W)[idx];
    }
    // load x tile [128][128] into padded xs, zero-pad OOB rows
    #pragma unroll
    for (int t = 0; t < 8; t++) {
        int idx = tid + 512 * t;          // 0..4095
        int r  = idx >> 5;
        int c4 = idx & 31;
        float4 v = make_float4(0.f, 0.f, 0.f, 0.f);
        int row = m0 + r;
        if (row < NN) v = ((const float4*)x)[(size_t)row * 32 + c4];
        ((float4*)(xs + (size_t)r * XS_STRIDE))[c4] = v;
    }
    __syncthreads();

    float acc[8][4];
    #pragma unroll
    for (int i = 0; i < 8; i++)
        #pragma unroll
        for (int j = 0; j < 4; j++) acc[i][j] = 0.f;

    #pragma unroll 8
    for (int k = 0; k < 128; k++) {
        float av[8];
        #pragma unroll
        for (int i = 0; i < 8; i++) av[i] = xs[(ty + 16 * i) * XS_STRIDE + k];
        float4 b = ((float4*)(ws + k * 128))[tx];
        #pragma unroll
        for (int i = 0; i < 8; i++) {
            acc[i][0] = fmaf(av[i], b.x, acc[i][0]);
            acc[i][1] = fmaf(av[i], b.y, acc[i][1]);
            acc[i][2] = fmaf(av[i], b.z, acc[i][2]);
            acc[i][3] = fmaf(av[i], b.w, acc[i][3]);
        }
    }

    // attention vectors for this thread's 4 columns
    float4 s = ((const float4*)att_s)[tx];
    float4 d = ((const float4*)att_d)[tx];

    #pragma unroll
    for (int i = 0; i < 8; i++) {
        int row = m0 + ty + 16 * i;
        float4 hv = make_float4(acc[i][0], acc[i][1], acc[i][2], acc[i][3]);
        if (row < NN)
            ((float4*)(g_h + (size_t)row * 128))[tx] = hv;
        float ps = hv.x * s.x + hv.y * s.y + hv.z * s.z + hv.w * s.w;
        float pd = hv.x * d.x + hv.y * d.y + hv.z * d.z + hv.w * d.w;
        #pragma unroll
        for (int o = 16; o; o >>= 1) {
            ps += __shfl_xor_sync(0xffffffffu, ps, o);
            pd += __shfl_xor_sync(0xffffffffu, pd, o);
        }
        if (tx == 0 && row < NN) { g_as[row] = ps; g_ad[row] = pd; }
    }
}

// ---------------- 2) CSR build (fork stream — independent of GEMM) ----------------
__global__ void gat_zero_deg()
{
    int i = blockIdx.x * blockDim.x + threadIdx.x;
    if (i < NN) g_deg[i] = 0;
}

__global__ void gat_hist(const int* __restrict__ dst)
{
    int i = blockIdx.x * blockDim.x + threadIdx.x;
    if (i < EE) atomicAdd(&g_deg[dst[i]], 1);
}

// single block, 1024 threads: exclusive scan of degrees -> offsets + cursors
__global__ void gat_scan()
{
    __shared__ int s[1024];
    const int tid = threadIdx.x;
    const int C = (NN + 1023) / 1024;     // 49
    int start = tid * C;
    int end = start + C; if (end > NN) end = NN;
    if (start > NN) start = NN;

    int sum = 0;
    for (int i = start; i < end; i++) sum += g_deg[i];
    s[tid] = sum;
    for (int o = 1; o < 1024; o <<= 1) {
        __syncthreads();
        int v = (tid >= o) ? s[tid - o] : 0;
        __syncthreads();
        s[tid] += v;
    }
    __syncthreads();
    int run = s[tid] - sum;               // exclusive prefix
    for (int i = start; i < end; i++) {
        g_off[i] = run;
        g_cur[i] = run;
        run += g_deg[i];
    }
    if (tid == 1023) g_off[NN] = s[1023]; // = E
}

// assign CSR slot + scatter src index (no dependence on GEMM outputs)
__global__ void gat_build(const int* __restrict__ src, const int* __restrict__ dst)
{
    int i = blockIdx.x * blockDim.x + threadIdx.x;
    if (i >= EE) return;
    int dv = dst[i];
    int pos = atomicAdd(&g_cur[dv], 1);
    g_pos[i]    = pos;
    g_ssrc[pos] = src[i];
}

// ---------------- 3) per-edge p = exp(leakyrelu(a_s[src]+a_d[dst])) ----------------
// softmax is shift-invariant; logits are O(1) so no max-subtraction needed.
__global__ void gat_edge(const int* __restrict__ src, const int* __restrict__ dst)
{
    int i = blockIdx.x * blockDim.x + threadIdx.x;
    if (i >= EE) return;
    float t = g_as[src[i]] + g_ad[dst[i]];
    float e = t > 0.f ? t : NEG_SLOPE * t;
    g_es[g_pos[i]] = __expf(e);
}

// ---------------- 4) per-dst normalize + aggregate + fused epilogue ----------------
// one warp per destination node.
// Indices/weights for each 32-edge chunk are loaded LANE-PARALLEL (coalesced),
// then distributed via __shfl_sync — the h row gather is the only memory op in
// the inner loop, issued 4 independent 512B loads at a time.
__global__ void gat_aggregate(const float* __restrict__ x,
                              const float* __restrict__ bias,
                              const float* __restrict__ gamma,
                              const float* __restrict__ beta,
                              float* __restrict__ out)
{
    int u = blockIdx.x * (blockDim.x >> 5) + (threadIdx.x >> 5);
    int lane = threadIdx.x & 31;
    if (u >= NN) return;

    int o   = g_off[u];
    int deg = g_off[u + 1] - o;

    float4 acc = make_float4(0.f, 0.f, 0.f, 0.f);

    if (deg > 0) {
        // denominator (coalesced strided read)
        float sum = 0.f;
        for (int j = lane; j < deg; j += 32) sum += g_es[o + j];
        #pragma unroll
        for (int sh = 16; sh; sh >>= 1) sum += __shfl_xor_sync(0xffffffffu, sum, sh);
        float inv = 1.f / sum;

        // gather chunks of 32 edges: lane-parallel load, shfl distribute
        for (int base = 0; base < deg; base += 32) {
            int cnt = deg - base; if (cnt > 32) cnt = 32;
            int   sidx = 0; float pv = 0.f;
            if (lane < cnt) {
                sidx = g_ssrc[o + base + lane];       // coalesced
                pv   = g_es[o + base + lane] * inv;   // coalesced
            }
            int t = 0;
            for (; t + 4 <= cnt; t += 4) {
                int i0 = __shfl_sync(0xffffffffu, sidx, t + 0);
                int i1 = __shfl_sync(0xffffffffu, sidx, t + 1);
                int i2 = __shfl_sync(0xffffffffu, sidx, t + 2);
                int i3 = __shfl_sync(0xffffffffu, sidx, t + 3);
                float p0 = __shfl_sync(0xffffffffu, pv, t + 0);
                float p1 = __shfl_sync(0xffffffffu, pv, t + 1);
                float p2 = __shfl_sync(0xffffffffu, pv, t + 2);
                float p3 = __shfl_sync(0xffffffffu, pv, t + 3);
                float4 h0 = ((const float4*)(g_h + (size_t)i0 * 128))[lane];
                float4 h1 = ((const float4*)(g_h + (size_t)i1 * 128))[lane];
                float4 h2 = ((const float4*)(g_h + (size_t)i2 * 128))[lane];
                float4 h3 = ((const float4*)(g_h + (size_t)i3 * 128))[lane];
                acc.x = fmaf(p0, h0.x, acc.x); acc.y = fmaf(p0, h0.y, acc.y);
                acc.z = fmaf(p0, h0.z, acc.z); acc.w = fmaf(p0, h0.w, acc.w);
                acc.x = fmaf(p1, h1.x, acc.x); acc.y = fmaf(p1, h1.y, acc.y);
                acc.z = fmaf(p1, h1.z, acc.z); acc.w = fmaf(p1, h1.w, acc.w);
                acc.x = fmaf(p2, h2.x, acc.x); acc.y = fmaf(p2, h2.y, acc.y);
                acc.z = fmaf(p2, h2.z, acc.z); acc.w = fmaf(p2, h2.w, acc.w);
                acc.x = fmaf(p3, h3.x, acc.x); acc.y = fmaf(p3, h3.y, acc.y);
                acc.z = fmaf(p3, h3.z, acc.z); acc.w = fmaf(p3, h3.w, acc.w);
            }
            for (; t < cnt; t++) {
                int   it = __shfl_sync(0xffffffffu, sidx, t);
                float pt = __shfl_sync(0xffffffffu, pv, t);
                float4 ht = ((const float4*)(g_h + (size_t)it * 128))[lane];
                acc.x = fmaf(pt, ht.x, acc.x); acc.y = fmaf(pt, ht.y, acc.y);
                acc.z = fmaf(pt, ht.z, acc.z); acc.w = fmaf(pt, ht.w, acc.w);
            }
        }
    }

    // epilogue: bias -> BN(eval) -> ReLU -> residual
    const float inv_s = rsqrtf(1.0f + 1e-5f);
    float4 bv = ((const float4*)bias)[lane];
    float4 gv = ((const float4*)gamma)[lane];
    float4 be = ((const float4*)beta)[lane];
    float4 xv = ((const float4*)(x + (size_t)u * 128))[lane];

    float4 r;
    r.x = xv.x + fmaxf(gv.x * ((acc.x + bv.x) * inv_s) + be.x, 0.f);
    r.y = xv.y + fmaxf(gv.y * ((acc.y + bv.y) * inv_s) + be.y, 0.f);
    r.z = xv.z + fmaxf(gv.z * ((acc.z + bv.z) * inv_s) + be.z, 0.f);
    r.w = xv.w + fmaxf(gv.w * ((acc.w + bv.w) * inv_s) + be.w, 0.f);

    ((float4*)(out + (size_t)u * 128))[lane] = r;
}

// ---------------- stream/event handles (created pre-baseline, once) ----------------
struct StreamInit {
    cudaStream_t s;
    cudaEvent_t  eFork, eJoin;
    StreamInit() {
        cudaStreamCreateWithFlags(&s, cudaStreamNonBlocking);
        cudaEventCreateWithFlags(&eFork, cudaEventDisableTiming);
        cudaEventCreateWithFlags(&eJoin, cudaEventDisableTiming);
    }
};
static StreamInit g_si;

// ---------------- launch ----------------
extern "C" void kernel_launch(void* const* d_in, const int* in_sizes, int n_in,
                              void* d_out, int out_size)
{
    const float* x        = (const float*)d_in[0];
    const int*   edge     = (const int*)d_in[1];   // [2, E]: src row then dst row
    const float* W        = (const float*)d_in[2];
    const float* att_src  = (const float*)d_in[3];
    const float* att_dst  = (const float*)d_in[4];
    const float* bias     = (const float*)d_in[5];
    const float* gamma    = (const float*)d_in[6];
    const float* beta     = (const float*)d_in[7];
    float* out            = (float*)d_out;

    const int* src = edge;
    const int* dst = edge + EE;

    static const size_t GEMM_SMEM = (128 * XS_STRIDE + 128 * 128) * sizeof(float);
    cudaFuncSetAttribute(gat_gemm, cudaFuncAttributeMaxDynamicSharedMemorySize,
                         (int)GEMM_SMEM);

    // fork: full CSR structure build (depends only on edge_index), hidden under GEMM
    cudaEventRecord(g_si.eFork, 0);
    cudaStreamWaitEvent(g_si.s, g_si.eFork, 0);
    gat_zero_deg<<<(NN + 255) / 256, 256, 0, g_si.s>>>();
    gat_hist<<<(EE + 255) / 256, 256, 0, g_si.s>>>(dst);
    gat_scan<<<1, 1024, 0, g_si.s>>>();
    gat_build<<<(EE + 255) / 256, 256, 0, g_si.s>>>(src, dst);
    cudaEventRecord(g_si.eJoin, g_si.s);

    dim3 gemmBlock(32, 16);
    gat_gemm<<<(NN + 127) / 128, gemmBlock, GEMM_SMEM>>>(x, W, att_src, att_dst);

    // join: edge pass needs a_s/a_d (gemm) + slots (build)
    cudaStreamWaitEvent(0, g_si.eJoin, 0);
    gat_edge<<<(EE + 255) / 256, 256>>>(src, dst);

    gat_aggregate<<<(NN + 7) / 8, 256>>>(x, bias, gamma, beta, out);
}

// round 9
// speedup vs baseline: 1.5883x; 1.0753x over previous
#include <cuda_runtime.h>
#include <cuda_fp16.h>
#include <math_constants.h>

#define NN 50000
#define EE 800000
#define DD 128
#define NEG_SLOPE 0.2f
#define XS_STRIDE 132   // padded to break bank conflicts

// ---------------- device scratch (static, no allocation) ----------------
__device__ __half g_hh[(size_t)NN * DD]; // transformed features (fp16, only consumer is aggregate)
__device__ float g_as[NN];
__device__ float g_ad[NN];
__device__ int   g_deg[NN];
__device__ int   g_off[NN + 1];
__device__ int   g_cur[NN];
__device__ int   g_pos[EE];              // CSR slot per edge (built in fork stream)
__device__ int   g_ssrc[EE];             // edge src sorted by dst (fork stream)
__device__ float g_es[EE];               // exp(leaky(e)) sorted by dst

// ---------------- 1) GEMM: h = x @ W, fused a_s/a_d epilogue ----------------
// 128x128x128 tile, blockDim (32,16) = 512 thr, 8x4 microtile per thread.
// EMPIRICALLY the good config (R3: 183.3us total). Do not change the tile.
__global__ void gat_gemm(const float* __restrict__ x, const float* __restrict__ W,
                         const float* __restrict__ att_s, const float* __restrict__ att_d)
{
    extern __shared__ float sm[];
    float* xs = sm;                       // [128][XS_STRIDE]
    float* ws = sm + 128 * XS_STRIDE;     // [128][128] (k-major, same as W)

    const int tx = threadIdx.x, ty = threadIdx.y;
    const int tid = ty * 32 + tx;
    const int m0 = blockIdx.x * 128;

    // load W (128x128 = 4096 float4), 8 per thread
    #pragma unroll
    for (int t = 0; t < 8; t++) {
        int idx = tid + 512 * t;
        ((float4*)ws)[idx] = ((const float4*)W)[idx];
    }
    // load x tile [128][128] into padded xs, zero-pad OOB rows
    #pragma unroll
    for (int t = 0; t < 8; t++) {
        int idx = tid + 512 * t;          // 0..4095
        int r  = idx >> 5;
        int c4 = idx & 31;
        float4 v = make_float4(0.f, 0.f, 0.f, 0.f);
        int row = m0 + r;
        if (row < NN) v = ((const float4*)x)[(size_t)row * 32 + c4];
        ((float4*)(xs + (size_t)r * XS_STRIDE))[c4] = v;
    }
    __syncthreads();

    float acc[8][4];
    #pragma unroll
    for (int i = 0; i < 8; i++)
        #pragma unroll
        for (int j = 0; j < 4; j++) acc[i][j] = 0.f;

    #pragma unroll 8
    for (int k = 0; k < 128; k++) {
        float av[8];
        #pragma unroll
        for (int i = 0; i < 8; i++) av[i] = xs[(ty + 16 * i) * XS_STRIDE + k];
        float4 b = ((float4*)(ws + k * 128))[tx];
        #pragma unroll
        for (int i = 0; i < 8; i++) {
            acc[i][0] = fmaf(av[i], b.x, acc[i][0]);
            acc[i][1] = fmaf(av[i], b.y, acc[i][1]);
            acc[i][2] = fmaf(av[i], b.z, acc[i][2]);
            acc[i][3] = fmaf(av[i], b.w, acc[i][3]);
        }
    }

    // attention vectors for this thread's 4 columns
    float4 s = ((const float4*)att_s)[tx];
    float4 d = ((const float4*)att_d)[tx];

    #pragma unroll
    for (int i = 0; i < 8; i++) {
        int row = m0 + ty + 16 * i;
        float4 hv = make_float4(acc[i][0], acc[i][1], acc[i][2], acc[i][3]);
        if (row < NN) {
            __half2 hA = __floats2half2_rn(hv.x, hv.y);
            __half2 hB = __floats2half2_rn(hv.z, hv.w);
            uint2 pk;
            pk.x = *(const unsigned int*)&hA;
            pk.y = *(const unsigned int*)&hB;
            ((uint2*)(g_hh + (size_t)row * 128))[tx] = pk;
        }
        float ps = hv.x * s.x + hv.y * s.y + hv.z * s.z + hv.w * s.w;
        float pd = hv.x * d.x + hv.y * d.y + hv.z * d.z + hv.w * d.w;
        #pragma unroll
        for (int o = 16; o; o >>= 1) {
            ps += __shfl_xor_sync(0xffffffffu, ps, o);
            pd += __shfl_xor_sync(0xffffffffu, pd, o);
        }
        if (tx == 0 && row < NN) { g_as[row] = ps; g_ad[row] = pd; }
    }
}

// ---------------- 2) CSR build (fork stream — independent of GEMM) ----------------
__global__ void gat_zero_deg()
{
    int i = blockIdx.x * blockDim.x + threadIdx.x;
    if (i < NN) g_deg[i] = 0;
}

__global__ void gat_hist(const int* __restrict__ dst)
{
    int i = blockIdx.x * blockDim.x + threadIdx.x;
    if (i < EE) atomicAdd(&g_deg[dst[i]], 1);
}

// single block, 1024 threads: exclusive scan of degrees -> offsets + cursors
__global__ void gat_scan()
{
    __shared__ int s[1024];
    const int tid = threadIdx.x;
    const int C = (NN + 1023) / 1024;     // 49
    int start = tid * C;
    int end = start + C; if (end > NN) end = NN;
    if (start > NN) start = NN;

    int sum = 0;
    for (int i = start; i < end; i++) sum += g_deg[i];
    s[tid] = sum;
    for (int o = 1; o < 1024; o <<= 1) {
        __syncthreads();
        int v = (tid >= o) ? s[tid - o] : 0;
        __syncthreads();
        s[tid] += v;
    }
    __syncthreads();
    int run = s[tid] - sum;               // exclusive prefix
    for (int i = start; i < end; i++) {
        g_off[i] = run;
        g_cur[i] = run;
        run += g_deg[i];
    }
    if (tid == 1023) g_off[NN] = s[1023]; // = E
}

// assign CSR slot + scatter src index (no dependence on GEMM outputs)
__global__ void gat_build(const int* __restrict__ src, const int* __restrict__ dst)
{
    int i = blockIdx.x * blockDim.x + threadIdx.x;
    if (i >= EE) return;
    int dv = dst[i];
    int pos = atomicAdd(&g_cur[dv], 1);
    g_pos[i]    = pos;
    g_ssrc[pos] = src[i];
}

// ---------------- 3) per-edge p = exp(leakyrelu(a_s[src]+a_d[dst])) ----------------
// softmax is shift-invariant; logits are O(1) so no max-subtraction needed.
__global__ void gat_edge(const int* __restrict__ src, const int* __restrict__ dst)
{
    int i = blockIdx.x * blockDim.x + threadIdx.x;
    if (i >= EE) return;
    float t = g_as[src[i]] + g_ad[dst[i]];
    float e = t > 0.f ? t : NEG_SLOPE * t;
    g_es[g_pos[i]] = __expf(e);
}

// ---------------- 4) per-dst normalize + aggregate + fused epilogue ----------------
// one warp per destination node; gathers batched x4. h rows are fp16 (256B/row)
// to halve L2 gather traffic; accumulation in fp32.
__global__ void gat_aggregate(const float* __restrict__ x,
                              const float* __restrict__ bias,
                              const float* __restrict__ gamma,
                              const float* __restrict__ beta,
                              float* __restrict__ out)
{
    int u = blockIdx.x * (blockDim.x >> 5) + (threadIdx.x >> 5);
    int lane = threadIdx.x & 31;
    if (u >= NN) return;

    int o   = g_off[u];
    int deg = g_off[u + 1] - o;

    float4 acc = make_float4(0.f, 0.f, 0.f, 0.f);

    if (deg > 0) {
        // pass A: denom (contiguous)
        float sum = 0.f;
        for (int j = lane; j < deg; j += 32) sum += g_es[o + j];
        #pragma unroll
        for (int sh = 16; sh; sh >>= 1) sum += __shfl_xor_sync(0xffffffffu, sum, sh);
        float inv = 1.f / sum;

        // pass B: weighted gather, 4 edges in flight (fp16 rows)
        for (int j0 = 0; j0 < deg; j0 += 4) {
            float p4[4]; int s4[4];
            #pragma unroll
            for (int t = 0; t < 4; t++) {
                int j = j0 + t;
                bool v = j < deg;
                int jj = v ? j : 0;
                s4[t] = g_ssrc[o + jj];
                p4[t] = v ? g_es[o + jj] * inv : 0.f;
            }
            uint2 pk4[4];
            #pragma unroll
            for (int t = 0; t < 4; t++)
                pk4[t] = ((const uint2*)(g_hh + (size_t)s4[t] * 128))[lane];
            #pragma unroll
            for (int t = 0; t < 4; t++) {
                float2 f01 = __half22float2(*(const __half2*)&pk4[t].x);
                float2 f23 = __half22float2(*(const __half2*)&pk4[t].y);
                acc.x = fmaf(p4[t], f01.x, acc.x);
                acc.y = fmaf(p4[t], f01.y, acc.y);
                acc.z = fmaf(p4[t], f23.x, acc.z);
                acc.w = fmaf(p4[t], f23.y, acc.w);
            }
        }
    }

    // epilogue: bias -> BN(eval) -> ReLU -> residual
    const float inv_s = rsqrtf(1.0f + 1e-5f);
    float4 bv = ((const float4*)bias)[lane];
    float4 gv = ((const float4*)gamma)[lane];
    float4 be = ((const float4*)beta)[lane];
    float4 xv = ((const float4*)(x + (size_t)u * 128))[lane];

    float4 r;
    r.x = xv.x + fmaxf(gv.x * ((acc.x + bv.x) * inv_s) + be.x, 0.f);
    r.y = xv.y + fmaxf(gv.y * ((acc.y + bv.y) * inv_s) + be.y, 0.f);
    r.z = xv.z + fmaxf(gv.z * ((acc.z + bv.z) * inv_s) + be.z, 0.f);
    r.w = xv.w + fmaxf(gv.w * ((acc.w + bv.w) * inv_s) + be.w, 0.f);

    ((float4*)(out + (size_t)u * 128))[lane] = r;
}

// ---------------- stream/event handles (created pre-baseline, once) ----------------
struct StreamInit {
    cudaStream_t s;
    cudaEvent_t  eFork, eJoin;
    StreamInit() {
        cudaStreamCreateWithFlags(&s, cudaStreamNonBlocking);
        cudaEventCreateWithFlags(&eFork, cudaEventDisableTiming);
        cudaEventCreateWithFlags(&eJoin, cudaEventDisableTiming);
    }
};
static StreamInit g_si;

// ---------------- launch ----------------
extern "C" void kernel_launch(void* const* d_in, const int* in_sizes, int n_in,
                              void* d_out, int out_size)
{
    const float* x        = (const float*)d_in[0];
    const int*   edge     = (const int*)d_in[1];   // [2, E]: src row then dst row
    const float* W        = (const float*)d_in[2];
    const float* att_src  = (const float*)d_in[3];
    const float* att_dst  = (const float*)d_in[4];
    const float* bias     = (const float*)d_in[5];
    const float* gamma    = (const float*)d_in[6];
    const float* beta     = (const float*)d_in[7];
    float* out            = (float*)d_out;

    const int* src = edge;
    const int* dst = edge + EE;

    static const size_t GEMM_SMEM = (128 * XS_STRIDE + 128 * 128) * sizeof(float);
    cudaFuncSetAttribute(gat_gemm, cudaFuncAttributeMaxDynamicSharedMemorySize,
                         (int)GEMM_SMEM);

    // fork: full CSR structure build (depends only on edge_index), hidden under GEMM
    cudaEventRecord(g_si.eFork, 0);
    cudaStreamWaitEvent(g_si.s, g_si.eFork, 0);
    gat_zero_deg<<<(NN + 255) / 256, 256, 0, g_si.s>>>();
    gat_hist<<<(EE + 255) / 256, 256, 0, g_si.s>>>(dst);
    gat_scan<<<1, 1024, 0, g_si.s>>>();
    gat_build<<<(EE + 255) / 256, 256, 0, g_si.s>>>(src, dst);
    cudaEventRecord(g_si.eJoin, g_si.s);

    dim3 gemmBlock(32, 16);
    gat_gemm<<<(NN + 127) / 128, gemmBlock, GEMM_SMEM>>>(x, W, att_src, att_dst);

    // join: edge pass needs a_s/a_d (gemm) + slots (build)
    cudaStreamWaitEvent(0, g_si.eJoin, 0);
    gat_edge<<<(EE + 255) / 256, 256>>>(src, dst);

    gat_aggregate<<<(NN + 7) / 8, 256>>>(x, bias, gamma, beta, out);
}

// round 10
// speedup vs baseline: 1.6221x; 1.0212x over previous
#include <cuda_runtime.h>
#include <cuda_fp16.h>
#include <math_constants.h>

#define NN 50000
#define EE 800000
#define DD 128
#define NEG_SLOPE 0.2f
#define HS 136          // smem half-stride (conflict-free for quad fragment loads)

// ---------------- device scratch (static, no allocation) ----------------
__device__ __half g_hh[(size_t)NN * DD]; // transformed features (fp16)
__device__ __half g_wh[DD * DD];         // W^T in fp16: g_wh[n*DD + k]
__device__ float g_as[NN];
__device__ float g_ad[NN];
__device__ int   g_deg[NN];
__device__ int   g_off[NN + 1];
__device__ int   g_cur[NN];
__device__ int   g_pos[EE];
__device__ int   g_ssrc[EE];
__device__ float g_es[EE];

// ---------------- 0) W -> fp16 transposed (tiny, once per launch) ----------------
__global__ void gat_wconv(const float* __restrict__ W)
{
    int i = blockIdx.x * blockDim.x + threadIdx.x;   // over DD*DD
    if (i < DD * DD) {
        int k = i >> 7, n = i & 127;                 // W[k][n]
        g_wh[n * DD + k] = __float2half(W[i]);
    }
}

// ---------------- 1) HMMA GEMM: h = x @ W (fp16 in, fp32 acc) ----------------
// 128x128x128 tile, 256 thr = 8 warps (4 m-warps x 2 n-warps).
// Each warp: 2 m-atoms x 8 n-atoms of mma.m16n8k16. Fused a_s/a_d epilogue
// from fp32 accumulators; h stored fp16 via smem staging.
__global__ void gat_gemm_hmma(const float* __restrict__ x,
                              const float* __restrict__ att_s,
                              const float* __restrict__ att_d)
{
    extern __shared__ char smbuf[];
    __half* As = (__half*)smbuf;                 // [128][HS]
    __half* Bs = As + 128 * HS;                  // [128][HS] (n-major: Bs[n][k])
    float*  s_as = (float*)(Bs + 128 * HS);      // [128]
    float*  s_ad = s_as + 128;                   // [128]

    const int tid  = threadIdx.x;
    const int wid  = tid >> 5;
    const int lane = tid & 31;
    const int g    = lane >> 2;                  // group id (0..7)
    const int tg   = lane & 3;                   // thread-in-group
    const int m0   = blockIdx.x * 128;
    const int warp_m = wid & 3;                  // 0..3 (32 rows each)
    const int warp_n = wid >> 2;                 // 0..1 (64 cols each)

    if (tid < 128) { s_as[tid] = 0.f; s_ad[tid] = 0.f; }

    // load x tile fp32 -> fp16 into As (zero-pad OOB rows)
    #pragma unroll
    for (int t = 0; t < 16; t++) {
        int idx = tid + 256 * t;                 // float4 id over [128][32]
        int r = idx >> 5, c4 = idx & 31;
        float4 v = make_float4(0.f, 0.f, 0.f, 0.f);
        int row = m0 + r;
        if (row < NN) v = ((const float4*)x)[(size_t)row * 32 + c4];
        __half2 h0 = __floats2half2_rn(v.x, v.y);
        __half2 h1 = __floats2half2_rn(v.z, v.w);
        uint2 pk;
        pk.x = *(const unsigned int*)&h0;
        pk.y = *(const unsigned int*)&h1;
        *(uint2*)&As[r * HS + c4 * 4] = pk;
    }
    // load W^T fp16 into Bs (coalesced uint4)
    #pragma unroll
    for (int t = 0; t < 8; t++) {
        int idx = tid + 256 * t;                 // uint4 id over [128][16]
        int r = idx >> 4, c8 = idx & 15;
        uint4 v = ((const uint4*)g_wh)[idx];
        *(uint4*)&Bs[r * HS + c8 * 8] = v;
    }
    __syncthreads();

    float acc[2][8][4];
    #pragma unroll
    for (int mi = 0; mi < 2; mi++)
        #pragma unroll
        for (int ni = 0; ni < 8; ni++)
            #pragma unroll
            for (int q = 0; q < 4; q++) acc[mi][ni][q] = 0.f;

    #pragma unroll
    for (int ks = 0; ks < 8; ks++) {
        const int k0 = ks * 16;
        unsigned int a[2][4];
        #pragma unroll
        for (int mi = 0; mi < 2; mi++) {
            int r = warp_m * 32 + mi * 16;
            a[mi][0] = *(const unsigned int*)&As[(r + g)     * HS + k0 +     tg * 2];
            a[mi][1] = *(const unsigned int*)&As[(r + g + 8) * HS + k0 +     tg * 2];
            a[mi][2] = *(const unsigned int*)&As[(r + g)     * HS + k0 + 8 + tg * 2];
            a[mi][3] = *(const unsigned int*)&As[(r + g + 8) * HS + k0 + 8 + tg * 2];
        }
        #pragma unroll
        for (int ni = 0; ni < 8; ni++) {
            int n = warp_n * 64 + ni * 8 + g;
            unsigned int b0 = *(const unsigned int*)&Bs[n * HS + k0 +     tg * 2];
            unsigned int b1 = *(const unsigned int*)&Bs[n * HS + k0 + 8 + tg * 2];
            #pragma unroll
            for (int mi = 0; mi < 2; mi++) {
                asm volatile(
                    "mma.sync.aligned.m16n8k16.row.col.f32.f16.f16.f32 "
                    "{%0,%1,%2,%3}, {%4,%5,%6,%7}, {%8,%9}, {%0,%1,%2,%3};"
                    : "+f"(acc[mi][ni][0]), "+f"(acc[mi][ni][1]),
                      "+f"(acc[mi][ni][2]), "+f"(acc[mi][ni][3])
                    : "r"(a[mi][0]), "r"(a[mi][1]), "r"(a[mi][2]), "r"(a[mi][3]),
                      "r"(b0), "r"(b1));
            }
        }
    }

    // ---- a_s / a_d partial dots from fp32 accumulators ----
    float ps[2][2] = {{0.f,0.f},{0.f,0.f}};
    float pd[2][2] = {{0.f,0.f},{0.f,0.f}};
    #pragma unroll
    for (int ni = 0; ni < 8; ni++) {
        int n = warp_n * 64 + ni * 8 + tg * 2;
        float sa0 = att_s[n], sa1 = att_s[n + 1];
        float da0 = att_d[n], da1 = att_d[n + 1];
        #pragma unroll
        for (int mi = 0; mi < 2; mi++) {
            ps[mi][0] = fmaf(acc[mi][ni][0], sa0, fmaf(acc[mi][ni][1], sa1, ps[mi][0]));
            ps[mi][1] = fmaf(acc[mi][ni][2], sa0, fmaf(acc[mi][ni][3], sa1, ps[mi][1]));
            pd[mi][0] = fmaf(acc[mi][ni][0], da0, fmaf(acc[mi][ni][1], da1, pd[mi][0]));
            pd[mi][1] = fmaf(acc[mi][ni][2], da0, fmaf(acc[mi][ni][3], da1, pd[mi][1]));
        }
    }
    // quad reduce (over tg = lane bits 0..1)
    #pragma unroll
    for (int sh = 1; sh <= 2; sh <<= 1) {
        #pragma unroll
        for (int mi = 0; mi < 2; mi++) {
            ps[mi][0] += __shfl_xor_sync(0xffffffffu, ps[mi][0], sh);
            ps[mi][1] += __shfl_xor_sync(0xffffffffu, ps[mi][1], sh);
            pd[mi][0] += __shfl_xor_sync(0xffffffffu, pd[mi][0], sh);
            pd[mi][1] += __shfl_xor_sync(0xffffffffu, pd[mi][1], sh);
        }
    }
    if (tg == 0) {
        #pragma unroll
        for (int mi = 0; mi < 2; mi++) {
            int r = warp_m * 32 + mi * 16 + g;
            atomicAdd(&s_as[r],     ps[mi][0]);
            atomicAdd(&s_as[r + 8], ps[mi][1]);
            atomicAdd(&s_ad[r],     pd[mi][0]);
            atomicAdd(&s_ad[r + 8], pd[mi][1]);
        }
    }

    // ---- stage h (fp16) into As, then coalesced store ----
    __syncthreads();          // all warps done reading As/Bs
    #pragma unroll
    for (int mi = 0; mi < 2; mi++) {
        #pragma unroll
        for (int ni = 0; ni < 8; ni++) {
            int r0 = warp_m * 32 + mi * 16 + g;
            int n  = warp_n * 64 + ni * 8 + tg * 2;
            __half2 h01 = __floats2half2_rn(acc[mi][ni][0], acc[mi][ni][1]);
            __half2 h23 = __floats2half2_rn(acc[mi][ni][2], acc[mi][ni][3]);
            *(__half2*)&As[r0 * HS + n]       = h01;
            *(__half2*)&As[(r0 + 8) * HS + n] = h23;
        }
    }
    __syncthreads();
    #pragma unroll
    for (int t = 0; t < 8; t++) {
        int idx = tid + 256 * t;                 // uint4 id over [128][16]
        int r = idx >> 4, c = idx & 15;
        int row = m0 + r;
        if (row < NN)
            ((uint4*)(g_hh + (size_t)row * 128))[c] = *(const uint4*)&As[r * HS + c * 8];
    }
    if (tid < 128) {
        int row = m0 + tid;
        if (row < NN) { g_as[row] = s_as[tid]; g_ad[row] = s_ad[tid]; }
    }
}

// ---------------- 2) CSR build (fork stream — independent of GEMM) ----------------
__global__ void gat_zero_deg()
{
    int i = blockIdx.x * blockDim.x + threadIdx.x;
    if (i < NN) g_deg[i] = 0;
}

__global__ void gat_hist(const int* __restrict__ dst)
{
    int i = blockIdx.x * blockDim.x + threadIdx.x;
    if (i < EE) atomicAdd(&g_deg[dst[i]], 1);
}

__global__ void gat_scan()
{
    __shared__ int s[1024];
    const int tid = threadIdx.x;
    const int C = (NN + 1023) / 1024;
    int start = tid * C;
    int end = start + C; if (end > NN) end = NN;
    if (start > NN) start = NN;

    int sum = 0;
    for (int i = start; i < end; i++) sum += g_deg[i];
    s[tid] = sum;
    for (int o = 1; o < 1024; o <<= 1) {
        __syncthreads();
        int v = (tid >= o) ? s[tid - o] : 0;
        __syncthreads();
        s[tid] += v;
    }
    __syncthreads();
    int run = s[tid] - sum;
    for (int i = start; i < end; i++) {
        g_off[i] = run;
        g_cur[i] = run;
        run += g_deg[i];
    }
    if (tid == 1023) g_off[NN] = s[1023];
}

__global__ void gat_build(const int* __restrict__ src, const int* __restrict__ dst)
{
    int i = blockIdx.x * blockDim.x + threadIdx.x;
    if (i >= EE) return;
    int dv = dst[i];
    int pos = atomicAdd(&g_cur[dv], 1);
    g_pos[i]    = pos;
    g_ssrc[pos] = src[i];
}

// ---------------- 3) per-edge p = exp(leakyrelu(a_s[src]+a_d[dst])) ----------------
__global__ void gat_edge(const int* __restrict__ src, const int* __restrict__ dst)
{
    int i = blockIdx.x * blockDim.x + threadIdx.x;
    if (i >= EE) return;
    float t = g_as[src[i]] + g_ad[dst[i]];
    float e = t > 0.f ? t : NEG_SLOPE * t;
    g_es[g_pos[i]] = __expf(e);
}

// ---------------- 4) per-dst normalize + aggregate + fused epilogue ----------------
__global__ void gat_aggregate(const float* __restrict__ x,
                              const float* __restrict__ bias,
                              const float* __restrict__ gamma,
                              const float* __restrict__ beta,
                              float* __restrict__ out)
{
    int u = blockIdx.x * (blockDim.x >> 5) + (threadIdx.x >> 5);
    int lane = threadIdx.x & 31;
    if (u >= NN) return;

    int o   = g_off[u];
    int deg = g_off[u + 1] - o;

    float4 acc = make_float4(0.f, 0.f, 0.f, 0.f);

    if (deg > 0) {
        float sum = 0.f;
        for (int j = lane; j < deg; j += 32) sum += g_es[o + j];
        #pragma unroll
        for (int sh = 16; sh; sh >>= 1) sum += __shfl_xor_sync(0xffffffffu, sum, sh);
        float inv = 1.f / sum;

        for (int j0 = 0; j0 < deg; j0 += 4) {
            float p4[4]; int s4[4];
            #pragma unroll
            for (int t = 0; t < 4; t++) {
                int j = j0 + t;
                bool v = j < deg;
                int jj = v ? j : 0;
                s4[t] = g_ssrc[o + jj];
                p4[t] = v ? g_es[o + jj] * inv : 0.f;
            }
            uint2 pk4[4];
            #pragma unroll
            for (int t = 0; t < 4; t++)
                pk4[t] = ((const uint2*)(g_hh + (size_t)s4[t] * 128))[lane];
            #pragma unroll
            for (int t = 0; t < 4; t++) {
                float2 f01 = __half22float2(*(const __half2*)&pk4[t].x);
                float2 f23 = __half22float2(*(const __half2*)&pk4[t].y);
                acc.x = fmaf(p4[t], f01.x, acc.x);
                acc.y = fmaf(p4[t], f01.y, acc.y);
                acc.z = fmaf(p4[t], f23.x, acc.z);
                acc.w = fmaf(p4[t], f23.y, acc.w);
            }
        }
    }

    const float inv_s = rsqrtf(1.0f + 1e-5f);
    float4 bv = ((const float4*)bias)[lane];
    float4 gv = ((const float4*)gamma)[lane];
    float4 be = ((const float4*)beta)[lane];
    float4 xv = ((const float4*)(x + (size_t)u * 128))[lane];

    float4 r;
    r.x = xv.x + fmaxf(gv.x * ((acc.x + bv.x) * inv_s) + be.x, 0.f);
    r.y = xv.y + fmaxf(gv.y * ((acc.y + bv.y) * inv_s) + be.y, 0.f);
    r.z = xv.z + fmaxf(gv.z * ((acc.z + bv.z) * inv_s) + be.z, 0.f);
    r.w = xv.w + fmaxf(gv.w * ((acc.w + bv.w) * inv_s) + be.w, 0.f);

    ((float4*)(out + (size_t)u * 128))[lane] = r;
}

// ---------------- stream/event handles (created pre-baseline, once) ----------------
struct StreamInit {
    cudaStream_t s;
    cudaEvent_t  eFork, eJoin;
    StreamInit() {
        cudaStreamCreateWithFlags(&s, cudaStreamNonBlocking);
        cudaEventCreateWithFlags(&eFork, cudaEventDisableTiming);
        cudaEventCreateWithFlags(&eJoin, cudaEventDisableTiming);
    }
};
static StreamInit g_si;

// ---------------- launch ----------------
extern "C" void kernel_launch(void* const* d_in, const int* in_sizes, int n_in,
                              void* d_out, int out_size)
{
    const float* x        = (const float*)d_in[0];
    const int*   edge     = (const int*)d_in[1];
    const float* W        = (const float*)d_in[2];
    const float* att_src  = (const float*)d_in[3];
    const float* att_dst  = (const float*)d_in[4];
    const float* bias     = (const float*)d_in[5];
    const float* gamma    = (const float*)d_in[6];
    const float* beta     = (const float*)d_in[7];
    float* out            = (float*)d_out;

    const int* src = edge;
    const int* dst = edge + EE;

    static const size_t GEMM_SMEM = (size_t)(2 * 128 * HS) * sizeof(__half)
                                  + 2 * 128 * sizeof(float);
    cudaFuncSetAttribute(gat_gemm_hmma, cudaFuncAttributeMaxDynamicSharedMemorySize,
                         (int)GEMM_SMEM);

    // fork: full CSR structure build (depends only on edge_index), hidden under GEMM
    cudaEventRecord(g_si.eFork, 0);
    cudaStreamWaitEvent(g_si.s, g_si.eFork, 0);
    gat_zero_deg<<<(NN + 255) / 256, 256, 0, g_si.s>>>();
    gat_hist<<<(EE + 255) / 256, 256, 0, g_si.s>>>(dst);
    gat_scan<<<1, 1024, 0, g_si.s>>>();
    gat_build<<<(EE + 255) / 256, 256, 0, g_si.s>>>(src, dst);
    cudaEventRecord(g_si.eJoin, g_si.s);

    gat_wconv<<<(DD * DD + 255) / 256, 256>>>(W);
    gat_gemm_hmma<<<(NN + 127) / 128, 256, GEMM_SMEM>>>(x, att_src, att_dst);

    // join: edge pass needs a_s/a_d (gemm) + slots (build)
    cudaStreamWaitEvent(0, g_si.eJoin, 0);
    gat_edge<<<(EE + 255) / 256, 256>>>(src, dst);

    gat_aggregate<<<(NN + 7) / 8, 256>>>(x, bias, gamma, beta, out);
}